// round 7
// baseline (speedup 1.0000x reference)
#include <cuda_runtime.h>
#include <math.h>

// Problem constants
#define Bsz    2
#define Nsz    256
#define Fsz    64
#define Hsz    64
#define NHEADS 4
#define Csz    256            // NHEADS * Hsz
#define EPSf   1e-5f
#define INFf   1e5f
#define HE_STRIDE 68          // 256x64 h_e row buffer, padded (68 mod 32 = 4 -> conflict-free f4)

// Scratch: per-node precomputed first-layer partials (A = h@W1_top, Bv = h@W1_bot + b1)
__device__ float g_A [Bsz * Nsz * Hsz];
__device__ float g_Bv[Bsz * Nsz * Hsz];

__device__ __forceinline__ float siluf(float xv) {
    return xv / (1.0f + __expf(-xv));
}

// ---------------------------------------------------------------------------
// Kernel 0: per-node precompute of edge-MLP layer-1 partials.
// grid = B*N blocks, 64 threads.
// ---------------------------------------------------------------------------
__global__ void sake_pre_kernel(const float* __restrict__ h,
                                const float* __restrict__ edge_w1,
                                const float* __restrict__ edge_b1) {
    int row = blockIdx.x;           // b*N + n
    int t = threadIdx.x;            // output dim o (0..63)
    __shared__ float sh[64];
    sh[t] = h[row * 64 + t];
    __syncthreads();
    float a  = 0.0f;
    float bv = edge_b1[t];
    #pragma unroll
    for (int k = 0; k < 64; k++) {
        float hv = sh[k];
        a  += hv * edge_w1[k * 64 + t];            // W1 rows 0..63   (h_j part)
        bv += hv * edge_w1[(64 + k) * 64 + t];     // W1 rows 64..127 (h_i part)
    }
    g_A [row * 64 + t] = a;
    g_Bv[row * 64 + t] = bv;
}

// ---------------------------------------------------------------------------
// Block reductions over 256 threads (8 warps) for float4 (4 heads at once)
// ---------------------------------------------------------------------------
__device__ __forceinline__ float4 warpRed4(float4 v, bool is_max) {
    #pragma unroll
    for (int off = 16; off; off >>= 1) {
        float ax = __shfl_xor_sync(0xffffffffu, v.x, off);
        float ay = __shfl_xor_sync(0xffffffffu, v.y, off);
        float az = __shfl_xor_sync(0xffffffffu, v.z, off);
        float aw = __shfl_xor_sync(0xffffffffu, v.w, off);
        if (is_max) { v.x = fmaxf(v.x, ax); v.y = fmaxf(v.y, ay); v.z = fmaxf(v.z, az); v.w = fmaxf(v.w, aw); }
        else        { v.x += ax;            v.y += ay;            v.z += az;            v.w += aw; }
    }
    return v;
}

// scratch must hold 9 float4 (36 floats)
__device__ __forceinline__ float4 blockRed4(float4 v, float* scratch, bool is_max) {
    int t = threadIdx.x, lane = t & 31, wid = t >> 5;
    v = warpRed4(v, is_max);
    __syncthreads();                       // protect scratch reuse across calls
    if (lane == 0) ((float4*)scratch)[wid] = v;
    __syncthreads();
    if (t < 8) {
        float4 w = ((float4*)scratch)[t];
        #pragma unroll
        for (int off = 4; off; off >>= 1) {
            float ax = __shfl_xor_sync(0x000000ffu, w.x, off, 8);
            float ay = __shfl_xor_sync(0x000000ffu, w.y, off, 8);
            float az = __shfl_xor_sync(0x000000ffu, w.z, off, 8);
            float aw = __shfl_xor_sync(0x000000ffu, w.w, off, 8);
            if (is_max) { w.x = fmaxf(w.x, ax); w.y = fmaxf(w.y, ay); w.z = fmaxf(w.z, az); w.w = fmaxf(w.w, aw); }
            else        { w.x += ax;            w.y += ay;            w.z += az;            w.w += aw; }
        }
        if (t == 0) ((float4*)scratch)[8] = w;
    }
    __syncthreads();
    return ((float4*)scratch)[8];
}

// ---------------------------------------------------------------------------
// Main kernel: one block per (b, i) row.
// ---------------------------------------------------------------------------
#define SM_HE    0
#define SM_ACT   (SM_HE   + 256*HE_STRIDE)
#define SM_DIST  (SM_ACT  + 512)
#define SM_UNIT  (SM_DIST + 256)
#define SM_ATT   (SM_UNIT + 1024)
#define SM_BVI   (SM_ATT  + 1024)
#define SM_W1L   (SM_BVI  + 64)
#define SM_B2    (SM_W1L  + 64)
#define SM_SEMW  (SM_B2   + 64)
#define SM_HI    (SM_SEMW + 256)
#define SM_AGG   (SM_HI   + 64)
#define SM_CN    (SM_AGG  + 256)
#define SM_H1    (SM_CN   + 256)
#define SM_HC    (SM_H1   + 64)
#define SM_HN    (SM_HC   + 64)
#define SM_RED   (SM_HN   + 64)
#define SM_MISC  (SM_RED  + 36)
#define SM_TOTAL (SM_MISC + 16)
#define SMEM_BYTES (SM_TOTAL * 4)

extern __shared__ float smem[];

__global__ __launch_bounds__(256, 2)
void sake_main_kernel(const float* __restrict__ h,
                      const float* __restrict__ x,
                      const float* __restrict__ v,
                      const float* __restrict__ edge_w1,
                      const float* __restrict__ edge_w2,
                      const float* __restrict__ edge_b2,
                      const float* __restrict__ sem_w,
                      const float* __restrict__ sem_b,
                      const float* __restrict__ post_w1,
                      const float* __restrict__ post_b1,
                      const float* __restrict__ post_w2,
                      const float* __restrict__ post_b2,
                      const float* __restrict__ node_w1,
                      const float* __restrict__ node_b1,
                      const float* __restrict__ node_w2,
                      const float* __restrict__ node_b2,
                      const float* __restrict__ vel_w1,
                      const float* __restrict__ vel_b1,
                      const float* __restrict__ vel_w2,
                      const float* __restrict__ vmix_w,
                      const float* __restrict__ log_gamma,
                      float* __restrict__ out) {
    const int blk = blockIdx.x;
    const int b = blk >> 8;
    const int i = blk & 255;
    const int t = threadIdx.x;
    const int row_i = b * Nsz + i;

    float* s_he   = smem + SM_HE;
    float* s_act  = smem + SM_ACT;
    float* s_dist = smem + SM_DIST;
    float* s_unit = smem + SM_UNIT;
    float* s_att  = smem + SM_ATT;
    float* s_Bvi  = smem + SM_BVI;
    float* s_w1l  = smem + SM_W1L;
    float* s_b2   = smem + SM_B2;
    float* s_semw = smem + SM_SEMW;
    float* s_hi   = smem + SM_HI;
    float* s_agg  = smem + SM_AGG;
    float* s_cn   = smem + SM_CN;
    float* s_h1   = smem + SM_H1;
    float* s_hc   = smem + SM_HC;
    float* s_hn   = smem + SM_HN;
    float* s_red  = smem + SM_RED;
    float* s_misc = smem + SM_MISC;

    // ---- init: per-row constants ----
    if (t < 64) {
        s_Bvi[t] = g_Bv[row_i * 64 + t];
        s_w1l[t] = edge_w1[128 * 64 + t];   // distance row of W1
        s_b2 [t] = edge_b2[t];
        s_hi [t] = h[row_i * 64 + t];
    }
    s_semw[t] = sem_w[t];                   // [64,4] row-major, 256 vals
    if (t < 4) {
        s_misc[t]     = __expf(log_gamma[t]);
        s_misc[4 + t] = sem_b[t];
    }

    // dists and unit vectors (thread j = t)
    {
        const float xi0 = x[row_i * 3 + 0];
        const float xi1 = x[row_i * 3 + 1];
        const float xi2 = x[row_i * 3 + 2];
        const int j = t;
        const int row_j = b * Nsz + j;
        float dx = x[row_j * 3 + 0] - xi0;
        float dy = x[row_j * 3 + 1] - xi1;
        float dz = x[row_j * 3 + 2] - xi2;
        float xn = sqrtf(dx * dx + dy * dy + dz * dz + EPSf);
        s_dist[j] = xn;
        float inv = 1.0f / (xn + EPSf);
        s_unit[j * 4 + 0] = dx * inv;
        s_unit[j * 4 + 1] = dy * inv;
        s_unit[j * 4 + 2] = dz * inv;
        s_unit[j * 4 + 3] = 0.0f;
    }

    // preload A[j] into the h_e buffer (overwritten in place by the MLP)
    for (int idx = t; idx < 256 * 64; idx += 256) {
        int j = idx >> 6, o = idx & 63;
        s_he[j * HE_STRIDE + o] = g_A[b * Nsz * 64 + idx];
    }

    // stage edge_w2 column o into registers
    const int o  = t & 63;
    const int jl = t >> 6;
    float w2[64];
    #pragma unroll
    for (int k = 0; k < 64; k++) w2[k] = edge_w2[k * 64 + o];
    __syncthreads();

    // ---- edge MLP over all j (4 j per iteration, double-buffered act1) ----
    for (int jb = 0; jb < 256; jb += 4) {
        const int j = jb + jl;
        float* act = s_act + ((jb >> 2) & 1) * 256 + jl * 64;
        float pre = s_he[j * HE_STRIDE + o] + s_Bvi[o] + s_dist[j] * s_w1l[o];
        act[o] = siluf(pre);
        __syncthreads();
        float acc = s_b2[o];
        const float4* a4 = (const float4*)act;
        #pragma unroll
        for (int k4 = 0; k4 < 16; k4++) {
            float4 a = a4[k4];
            acc += a.x * w2[4 * k4 + 0];
            acc += a.y * w2[4 * k4 + 1];
            acc += a.z * w2[4 * k4 + 2];
            acc += a.w * w2[4 * k4 + 3];
        }
        s_he[j * HE_STRIDE + o] = siluf(acc);
    }
    __syncthreads();

    // ---- semantic logits + three chained softmaxes (thread j = t) ----
    {
        const int j = t;
        const float4* her = (const float4*)(s_he + j * HE_STRIDE);
        const float4* sw  = (const float4*)s_semw;
        float4 sl = make_float4(s_misc[4], s_misc[5], s_misc[6], s_misc[7]);
        #pragma unroll
        for (int k4 = 0; k4 < 16; k4++) {
            float4 hv = her[k4];
            float4 wa = sw[4 * k4 + 0];
            float4 wb = sw[4 * k4 + 1];
            float4 wc = sw[4 * k4 + 2];
            float4 wd = sw[4 * k4 + 3];
            sl.x += hv.x * wa.x + hv.y * wb.x + hv.z * wc.x + hv.w * wd.x;
            sl.y += hv.x * wa.y + hv.y * wb.y + hv.z * wc.y + hv.w * wd.y;
            sl.z += hv.x * wa.z + hv.y * wb.z + hv.z * wc.z + hv.w * wd.z;
            sl.w += hv.x * wa.w + hv.y * wb.w + hv.z * wc.w + hv.w * wd.w;
        }
        // LeakyReLU(0.2), then diagonal mask
        sl.x = (sl.x > 0.0f ? sl.x : 0.2f * sl.x);
        sl.y = (sl.y > 0.0f ? sl.y : 0.2f * sl.y);
        sl.z = (sl.z > 0.0f ? sl.z : 0.2f * sl.z);
        sl.w = (sl.w > 0.0f ? sl.w : 0.2f * sl.w);
        const float diag = (j == i) ? INFf : 0.0f;
        sl.x -= diag; sl.y -= diag; sl.z -= diag; sl.w -= diag;

        const float dmask = s_dist[j] + diag;
        float4 dl = make_float4(-dmask * s_misc[0], -dmask * s_misc[1],
                                -dmask * s_misc[2], -dmask * s_misc[3]);

        // euclid softmax over j
        float4 m = blockRed4(dl, s_red, true);
        float4 eu = make_float4(__expf(dl.x - m.x), __expf(dl.y - m.y),
                                __expf(dl.z - m.z), __expf(dl.w - m.w));
        float4 sm = blockRed4(eu, s_red, false);
        eu.x /= sm.x; eu.y /= sm.y; eu.z /= sm.z; eu.w /= sm.w;

        // semantic softmax over j
        m = blockRed4(sl, s_red, true);
        float4 se = make_float4(__expf(sl.x - m.x), __expf(sl.y - m.y),
                                __expf(sl.z - m.z), __expf(sl.w - m.w));
        sm = blockRed4(se, s_red, false);
        se.x /= sm.x; se.y /= sm.y; se.z /= sm.z; se.w /= sm.w;

        // combined softmax over j of (eu * se)
        float4 cl = make_float4(eu.x * se.x, eu.y * se.y, eu.z * se.z, eu.w * se.w);
        m = blockRed4(cl, s_red, true);
        float4 ce = make_float4(__expf(cl.x - m.x), __expf(cl.y - m.y),
                                __expf(cl.z - m.z), __expf(cl.w - m.w));
        sm = blockRed4(ce, s_red, false);
        s_att[j * 4 + 0] = ce.x / sm.x;
        s_att[j * 4 + 1] = ce.y / sm.y;
        s_att[j * 4 + 2] = ce.z / sm.z;
        s_att[j * 4 + 3] = ce.w / sm.w;
    }
    __syncthreads();

    // ---- weighted aggregations (thread c = t, c = f*NHEADS + hd) ----
    {
        const int f  = t >> 2;
        const int hd = t & 3;
        float agg = 0.0f, a0 = 0.0f, a1 = 0.0f, a2 = 0.0f;
        const float* hep = s_he + f;
        #pragma unroll 8
        for (int j = 0; j < 256; j++) {
            float he = hep[j * HE_STRIDE];
            float at = s_att[j * 4 + hd];
            float w  = he * at;
            agg += w;
            a0 += w * s_unit[j * 4 + 0];
            a1 += w * s_unit[j * 4 + 1];
            a2 += w * s_unit[j * 4 + 2];
        }
        s_agg[t] = agg;
        const float invn = 1.0f / 256.0f;
        float c0 = a0 * invn, c1 = a1 * invn, c2 = a2 * invn;
        s_cn[t] = c0 * c0 + c1 * c1 + c2 * c2;
        float vm = vmix_w[t];
        float4 dv = make_float4(vm * c0, vm * c1, vm * c2, 0.0f);
        dv = blockRed4(dv, s_red, false);
        if (t == 0) { s_misc[8] = dv.x; s_misc[9] = dv.y; s_misc[10] = dv.z; }
    }
    __syncthreads();

    // ---- post MLP: comb_norm[256] -> 64 -> 64 ----
    if (t < 64) {
        float acc = post_b1[t];
        #pragma unroll 8
        for (int k = 0; k < 256; k++) acc += s_cn[k] * post_w1[k * 64 + t];
        s_h1[t] = siluf(acc);
    }
    __syncthreads();
    if (t < 64) {
        float acc = post_b2[t];
        #pragma unroll
        for (int k = 0; k < 64; k++) acc += s_h1[k] * post_w2[k * 64 + t];
        s_hc[t] = siluf(acc);
    }
    __syncthreads();

    // ---- node MLP: [h_i | h_agg | h_comb] (384) -> 64 -> 64, residual ----
    if (t < 64) {
        float acc = node_b1[t];
        #pragma unroll 8
        for (int k = 0; k < 64; k++)  acc += s_hi [k] * node_w1[k * 64 + t];
        #pragma unroll 8
        for (int k = 0; k < 256; k++) acc += s_agg[k] * node_w1[(64 + k) * 64 + t];
        #pragma unroll 8
        for (int k = 0; k < 64; k++)  acc += s_hc [k] * node_w1[(320 + k) * 64 + t];
        s_h1[t] = siluf(acc);
    }
    __syncthreads();
    if (t < 64) {
        float acc = node_b2[t];
        #pragma unroll
        for (int k = 0; k < 64; k++) acc += s_h1[k] * node_w2[k * 64 + t];
        float hn = s_hi[t] + siluf(acc);
        s_hn[t] = hn;
        out[row_i * 64 + t] = hn;             // h_new
    }
    __syncthreads();

    // ---- velocity / coordinate update ----
    if (t < 64) {
        float acc = vel_b1[t];
        #pragma unroll
        for (int k = 0; k < 64; k++) acc += s_hn[k] * vel_w1[k * 64 + t];
        float hv = siluf(acc) * vel_w2[t];
        #pragma unroll
        for (int off = 16; off; off >>= 1) hv += __shfl_xor_sync(0xffffffffu, hv, off);
        if ((t & 31) == 0) s_misc[12 + (t >> 5)] = hv;
    }
    __syncthreads();
    if (t < 3) {
        float vs = s_misc[12] + s_misc[13];
        float vnew = s_misc[8 + t] + vs * v[row_i * 3 + t];
        float xnew = x[row_i * 3 + t] + vnew;
        out[Bsz * Nsz * Fsz + row_i * 3 + t] = xnew;                       // x_new
        out[Bsz * Nsz * Fsz + Bsz * Nsz * 3 + row_i * 3 + t] = vnew;       // v_new
    }
}

// ---------------------------------------------------------------------------
extern "C" void kernel_launch(void* const* d_in, const int* in_sizes, int n_in,
                              void* d_out, int out_size) {
    (void)in_sizes; (void)n_in; (void)out_size;
    const float* h        = (const float*)d_in[0];
    const float* x        = (const float*)d_in[1];
    const float* v        = (const float*)d_in[2];
    const float* edge_w1  = (const float*)d_in[3];
    const float* edge_b1  = (const float*)d_in[4];
    const float* edge_w2  = (const float*)d_in[5];
    const float* edge_b2  = (const float*)d_in[6];
    const float* sem_w    = (const float*)d_in[7];
    const float* sem_b    = (const float*)d_in[8];
    const float* post_w1  = (const float*)d_in[9];
    const float* post_b1  = (const float*)d_in[10];
    const float* post_w2  = (const float*)d_in[11];
    const float* post_b2  = (const float*)d_in[12];
    const float* node_w1  = (const float*)d_in[13];
    const float* node_b1  = (const float*)d_in[14];
    const float* node_w2  = (const float*)d_in[15];
    const float* node_b2  = (const float*)d_in[16];
    const float* vel_w1   = (const float*)d_in[17];
    const float* vel_b1   = (const float*)d_in[18];
    const float* vel_w2   = (const float*)d_in[19];
    const float* vmix_w   = (const float*)d_in[20];
    const float* log_gamma= (const float*)d_in[21];
    float* out = (float*)d_out;

    cudaFuncSetAttribute(sake_main_kernel,
                         cudaFuncAttributeMaxDynamicSharedMemorySize, SMEM_BYTES);

    sake_pre_kernel<<<Bsz * Nsz, 64>>>(h, edge_w1, edge_b1);
    sake_main_kernel<<<Bsz * Nsz, 256, SMEM_BYTES>>>(
        h, x, v, edge_w1, edge_w2, edge_b2, sem_w, sem_b,
        post_w1, post_b1, post_w2, post_b2,
        node_w1, node_b1, node_w2, node_b2,
        vel_w1, vel_b1, vel_w2, vmix_w, log_gamma, out);
}

// round 10
// speedup vs baseline: 1.2106x; 1.2106x over previous
#include <cuda_runtime.h>
#include <math.h>

#define Bsz    2
#define Nsz    256
#define Fsz    64
#define Hsz    64
#define NHEADS 4
#define Csz    256
#define EPSf   1e-5f
#define INFf   1e5f
#define HE_STRIDE 68

__device__ float g_A [Bsz * Nsz * Hsz];
__device__ float g_Bv[Bsz * Nsz * Hsz];

__device__ __forceinline__ float siluf(float xv) {
    return xv / (1.0f + __expf(-xv));
}

// ---------------------------------------------------------------------------
__global__ void sake_pre_kernel(const float* __restrict__ h,
                                const float* __restrict__ edge_w1,
                                const float* __restrict__ edge_b1) {
    int row = blockIdx.x;
    int t = threadIdx.x;
    __shared__ float sh[64];
    sh[t] = h[row * 64 + t];
    __syncthreads();
    float a0 = 0.0f, a1 = 0.0f;
    float b0 = edge_b1[t], b1 = 0.0f;
    #pragma unroll
    for (int k = 0; k < 64; k += 2) {
        float h0 = sh[k], h1 = sh[k + 1];
        a0 += h0 * edge_w1[k * 64 + t];
        a1 += h1 * edge_w1[(k + 1) * 64 + t];
        b0 += h0 * edge_w1[(64 + k) * 64 + t];
        b1 += h1 * edge_w1[(64 + k + 1) * 64 + t];
    }
    g_A [row * 64 + t] = a0 + a1;
    g_Bv[row * 64 + t] = b0 + b1;
}

// ---------------------------------------------------------------------------
__device__ __forceinline__ float4 warpRed4(float4 v, bool is_max) {
    #pragma unroll
    for (int off = 16; off; off >>= 1) {
        float ax = __shfl_xor_sync(0xffffffffu, v.x, off);
        float ay = __shfl_xor_sync(0xffffffffu, v.y, off);
        float az = __shfl_xor_sync(0xffffffffu, v.z, off);
        float aw = __shfl_xor_sync(0xffffffffu, v.w, off);
        if (is_max) { v.x = fmaxf(v.x, ax); v.y = fmaxf(v.y, ay); v.z = fmaxf(v.z, az); v.w = fmaxf(v.w, aw); }
        else        { v.x += ax;            v.y += ay;            v.z += az;            v.w += aw; }
    }
    return v;
}

// scratch: 80 floats (16 float4 stage + 2 float4 results)
__device__ __forceinline__ float4 blockRed4(float4 v, float* scratch, bool is_max) {
    int t = threadIdx.x, lane = t & 31, wid = t >> 5;
    v = warpRed4(v, is_max);
    __syncthreads();
    if (lane == 0) ((float4*)scratch)[wid] = v;
    __syncthreads();
    if (t < 8) {
        float4 w = ((float4*)scratch)[t];
        #pragma unroll
        for (int off = 4; off; off >>= 1) {
            float ax = __shfl_xor_sync(0x000000ffu, w.x, off, 8);
            float ay = __shfl_xor_sync(0x000000ffu, w.y, off, 8);
            float az = __shfl_xor_sync(0x000000ffu, w.z, off, 8);
            float aw = __shfl_xor_sync(0x000000ffu, w.w, off, 8);
            if (is_max) { w.x = fmaxf(w.x, ax); w.y = fmaxf(w.y, ay); w.z = fmaxf(w.z, az); w.w = fmaxf(w.w, aw); }
            else        { w.x += ax;            w.y += ay;            w.z += az;            w.w += aw; }
        }
        if (t == 0) ((float4*)scratch)[16] = w;
    }
    __syncthreads();
    return ((float4*)scratch)[16];
}

// fused reduction of two float4 values (same op), same barrier count as one
__device__ __forceinline__ void blockRed4x2(float4& u, float4& w, float* scratch, bool is_max) {
    int t = threadIdx.x, lane = t & 31, wid = t >> 5;
    u = warpRed4(u, is_max);
    w = warpRed4(w, is_max);
    __syncthreads();
    if (lane == 0) {
        ((float4*)scratch)[wid * 2 + 0] = u;
        ((float4*)scratch)[wid * 2 + 1] = w;
    }
    __syncthreads();
    if (t < 8) {
        float4 a = ((float4*)scratch)[t * 2 + 0];
        float4 b = ((float4*)scratch)[t * 2 + 1];
        #pragma unroll
        for (int off = 4; off; off >>= 1) {
            float x0 = __shfl_xor_sync(0xffu, a.x, off, 8);
            float x1 = __shfl_xor_sync(0xffu, a.y, off, 8);
            float x2 = __shfl_xor_sync(0xffu, a.z, off, 8);
            float x3 = __shfl_xor_sync(0xffu, a.w, off, 8);
            float y0 = __shfl_xor_sync(0xffu, b.x, off, 8);
            float y1 = __shfl_xor_sync(0xffu, b.y, off, 8);
            float y2 = __shfl_xor_sync(0xffu, b.z, off, 8);
            float y3 = __shfl_xor_sync(0xffu, b.w, off, 8);
            if (is_max) {
                a.x = fmaxf(a.x, x0); a.y = fmaxf(a.y, x1); a.z = fmaxf(a.z, x2); a.w = fmaxf(a.w, x3);
                b.x = fmaxf(b.x, y0); b.y = fmaxf(b.y, y1); b.z = fmaxf(b.z, y2); b.w = fmaxf(b.w, y3);
            } else {
                a.x += x0; a.y += x1; a.z += x2; a.w += x3;
                b.x += y0; b.y += y1; b.z += y2; b.w += y3;
            }
        }
        if (t == 0) { ((float4*)scratch)[16] = a; ((float4*)scratch)[17] = b; }
    }
    __syncthreads();
    u = ((float4*)scratch)[16];
    w = ((float4*)scratch)[17];
}

// ---------------------------------------------------------------------------
#define SM_HE    0
#define SM_ACT   (SM_HE   + 256*HE_STRIDE)   // 2 halves x 2 parity x 4 slots x 64 = 1024
#define SM_DIST  (SM_ACT  + 1024)
#define SM_UNIT  (SM_DIST + 256)
#define SM_ATT   (SM_UNIT + 1024)            // reused as s_part in tail
#define SM_BVI   (SM_ATT  + 1024)
#define SM_W1L   (SM_BVI  + 64)
#define SM_B2    (SM_W1L  + 64)
#define SM_SEMW  (SM_B2   + 64)
#define SM_HI    (SM_SEMW + 256)
#define SM_AGG   (SM_HI   + 64)
#define SM_CN    (SM_AGG  + 256)
#define SM_H1    (SM_CN   + 256)
#define SM_HC    (SM_H1   + 64)
#define SM_HN    (SM_HC   + 64)
#define SM_RED   (SM_HN   + 64)              // 80 floats
#define SM_MISC  (SM_RED  + 80)
#define SM_TOTAL (SM_MISC + 16)
#define SMEM_BYTES (SM_TOTAL * 4)

extern __shared__ float smem[];

__global__ __launch_bounds__(256, 2)
void sake_main_kernel(const float* __restrict__ h,
                      const float* __restrict__ x,
                      const float* __restrict__ v,
                      const float* __restrict__ edge_w1,
                      const float* __restrict__ edge_w2,
                      const float* __restrict__ edge_b2,
                      const float* __restrict__ sem_w,
                      const float* __restrict__ sem_b,
                      const float* __restrict__ post_w1,
                      const float* __restrict__ post_b1,
                      const float* __restrict__ post_w2,
                      const float* __restrict__ post_b2,
                      const float* __restrict__ node_w1,
                      const float* __restrict__ node_b1,
                      const float* __restrict__ node_w2,
                      const float* __restrict__ node_b2,
                      const float* __restrict__ vel_w1,
                      const float* __restrict__ vel_b1,
                      const float* __restrict__ vel_w2,
                      const float* __restrict__ vmix_w,
                      const float* __restrict__ log_gamma,
                      float* __restrict__ out) {
    const int blk = blockIdx.x;
    const int b = blk >> 8;
    const int i = blk & 255;
    const int t = threadIdx.x;
    const int row_i = b * Nsz + i;

    float* s_he   = smem + SM_HE;
    float* s_act  = smem + SM_ACT;
    float* s_dist = smem + SM_DIST;
    float* s_unit = smem + SM_UNIT;
    float* s_att  = smem + SM_ATT;
    float* s_part = smem + SM_ATT;       // alias: s_att is dead when s_part is used
    float* s_Bvi  = smem + SM_BVI;
    float* s_w1l  = smem + SM_W1L;
    float* s_b2   = smem + SM_B2;
    float* s_semw = smem + SM_SEMW;
    float* s_hi   = smem + SM_HI;
    float* s_agg  = smem + SM_AGG;
    float* s_cn   = smem + SM_CN;
    float* s_h1   = smem + SM_H1;
    float* s_hc   = smem + SM_HC;
    float* s_hn   = smem + SM_HN;
    float* s_red  = smem + SM_RED;
    float* s_misc = smem + SM_MISC;

    // ---- init ----
    if (t < 64) {
        s_Bvi[t] = g_Bv[row_i * 64 + t];
        s_w1l[t] = edge_w1[128 * 64 + t];
        s_b2 [t] = edge_b2[t];
        s_hi [t] = h[row_i * 64 + t];
    }
    s_semw[t] = sem_w[t];
    if (t < 4) {
        s_misc[t]     = __expf(log_gamma[t]);
        s_misc[4 + t] = sem_b[t];
    }

    {
        const float xi0 = x[row_i * 3 + 0];
        const float xi1 = x[row_i * 3 + 1];
        const float xi2 = x[row_i * 3 + 2];
        const int j = t;
        const int row_j = b * Nsz + j;
        float dx = x[row_j * 3 + 0] - xi0;
        float dy = x[row_j * 3 + 1] - xi1;
        float dz = x[row_j * 3 + 2] - xi2;
        float xn = sqrtf(dx * dx + dy * dy + dz * dz + EPSf);
        s_dist[j] = xn;
        float inv = 1.0f / (xn + EPSf);
        s_unit[j * 4 + 0] = dx * inv;
        s_unit[j * 4 + 1] = dy * inv;
        s_unit[j * 4 + 2] = dz * inv;
        s_unit[j * 4 + 3] = 0.0f;
    }

    for (int idx = t; idx < 256 * 64; idx += 256) {
        int j = idx >> 6, o = idx & 63;
        s_he[j * HE_STRIDE + o] = g_A[b * Nsz * 64 + idx];
    }

    const int o    = t & 63;
    const int jl   = (t >> 6) & 1;
    const int half = t >> 7;
    float w2[64];
    #pragma unroll
    for (int k = 0; k < 64; k++) w2[k] = edge_w2[k * 64 + o];
    __syncthreads();

    // hoisted invariants (after barrier so producers are done)
    const float rBvi = s_Bvi[o];
    const float rw1l = s_w1l[o];
    const float rb2  = s_b2[o];

    // ---- edge MLP: two independent 128-thread halves, 4 j per half per iter,
    //      2 j per thread, named barriers, double-buffered act ----
    {
        const int jbase = half * 128;
        const int barid = 1 + half;
        for (int it = 0; it < 32; it++) {
            const int jA = jbase + it * 4 + jl;
            const int jB = jA + 2;
            float* actb = s_act + half * 512 + (it & 1) * 256;
            float preA = s_he[jA * HE_STRIDE + o] + rBvi + s_dist[jA] * rw1l;
            float preB = s_he[jB * HE_STRIDE + o] + rBvi + s_dist[jB] * rw1l;
            actb[jl * 64 + o]       = siluf(preA);
            actb[(2 + jl) * 64 + o] = siluf(preB);
            asm volatile("bar.sync %0, %1;" :: "r"(barid), "r"(128) : "memory");
            float a0 = 0.f, a1 = 0.f, a2 = 0.f, a3 = 0.f;
            float b0 = 0.f, b1 = 0.f, b2a = 0.f, b3 = 0.f;
            const float4* aA = (const float4*)(actb + jl * 64);
            const float4* aB = (const float4*)(actb + (2 + jl) * 64);
            #pragma unroll
            for (int k4 = 0; k4 < 16; k4 += 4) {
                float4 vA0 = aA[k4],     vB0 = aB[k4];
                float4 vA1 = aA[k4 + 1], vB1 = aB[k4 + 1];
                float4 vA2 = aA[k4 + 2], vB2 = aB[k4 + 2];
                float4 vA3 = aA[k4 + 3], vB3 = aB[k4 + 3];
                const float* wp = w2 + 4 * k4;
                a0 += vA0.x * wp[0]  + vA0.y * wp[1]  + vA0.z * wp[2]  + vA0.w * wp[3];
                b0 += vB0.x * wp[0]  + vB0.y * wp[1]  + vB0.z * wp[2]  + vB0.w * wp[3];
                a1 += vA1.x * wp[4]  + vA1.y * wp[5]  + vA1.z * wp[6]  + vA1.w * wp[7];
                b1 += vB1.x * wp[4]  + vB1.y * wp[5]  + vB1.z * wp[6]  + vB1.w * wp[7];
                a2 += vA2.x * wp[8]  + vA2.y * wp[9]  + vA2.z * wp[10] + vA2.w * wp[11];
                b2a += vB2.x * wp[8] + vB2.y * wp[9]  + vB2.z * wp[10] + vB2.w * wp[11];
                a3 += vA3.x * wp[12] + vA3.y * wp[13] + vA3.z * wp[14] + vA3.w * wp[15];
                b3 += vB3.x * wp[12] + vB3.y * wp[13] + vB3.z * wp[14] + vB3.w * wp[15];
            }
            s_he[jA * HE_STRIDE + o] = siluf(rb2 + (a0 + a1) + (a2 + a3));
            s_he[jB * HE_STRIDE + o] = siluf(rb2 + (b0 + b1) + (b2a + b3));
        }
    }
    __syncthreads();

    // ---- semantic logits + three chained softmaxes (thread j = t) ----
    {
        const int j = t;
        const float4* her = (const float4*)(s_he + j * HE_STRIDE);
        const float4* sw  = (const float4*)s_semw;
        float4 sl = make_float4(s_misc[4], s_misc[5], s_misc[6], s_misc[7]);
        #pragma unroll
        for (int k4 = 0; k4 < 16; k4++) {
            float4 hv = her[k4];
            float4 wa = sw[4 * k4 + 0];
            float4 wb = sw[4 * k4 + 1];
            float4 wc = sw[4 * k4 + 2];
            float4 wd = sw[4 * k4 + 3];
            sl.x += hv.x * wa.x + hv.y * wb.x + hv.z * wc.x + hv.w * wd.x;
            sl.y += hv.x * wa.y + hv.y * wb.y + hv.z * wc.y + hv.w * wd.y;
            sl.z += hv.x * wa.z + hv.y * wb.z + hv.z * wc.z + hv.w * wd.z;
            sl.w += hv.x * wa.w + hv.y * wb.w + hv.z * wc.w + hv.w * wd.w;
        }
        sl.x = (sl.x > 0.0f ? sl.x : 0.2f * sl.x);
        sl.y = (sl.y > 0.0f ? sl.y : 0.2f * sl.y);
        sl.z = (sl.z > 0.0f ? sl.z : 0.2f * sl.z);
        sl.w = (sl.w > 0.0f ? sl.w : 0.2f * sl.w);
        const float diag = (j == i) ? INFf : 0.0f;
        sl.x -= diag; sl.y -= diag; sl.z -= diag; sl.w -= diag;

        const float dmask = s_dist[j] + diag;
        float4 dl = make_float4(-dmask * s_misc[0], -dmask * s_misc[1],
                                -dmask * s_misc[2], -dmask * s_misc[3]);

        // fused max(dl), max(sl)
        float4 mdl = dl, msl = sl;
        blockRed4x2(mdl, msl, s_red, true);
        float4 eu = make_float4(__expf(dl.x - mdl.x), __expf(dl.y - mdl.y),
                                __expf(dl.z - mdl.z), __expf(dl.w - mdl.w));
        float4 se = make_float4(__expf(sl.x - msl.x), __expf(sl.y - msl.y),
                                __expf(sl.z - msl.z), __expf(sl.w - msl.w));
        // fused sum(eu), sum(se)
        float4 seu = eu, sse = se;
        blockRed4x2(seu, sse, s_red, false);
        eu.x /= seu.x; eu.y /= seu.y; eu.z /= seu.z; eu.w /= seu.w;
        se.x /= sse.x; se.y /= sse.y; se.z /= sse.z; se.w /= sse.w;

        float4 cl = make_float4(eu.x * se.x, eu.y * se.y, eu.z * se.z, eu.w * se.w);
        float4 m = blockRed4(cl, s_red, true);
        float4 ce = make_float4(__expf(cl.x - m.x), __expf(cl.y - m.y),
                                __expf(cl.z - m.z), __expf(cl.w - m.w));
        float4 sm = blockRed4(ce, s_red, false);
        s_att[j * 4 + 0] = ce.x / sm.x;
        s_att[j * 4 + 1] = ce.y / sm.y;
        s_att[j * 4 + 2] = ce.z / sm.z;
        s_att[j * 4 + 3] = ce.w / sm.w;
    }
    __syncthreads();

    // ---- weighted aggregations (thread c = t) ----
    {
        const int f  = t >> 2;
        const int hd = t & 3;
        float agg0 = 0.f, agg1 = 0.f;
        float a00 = 0.f, a01 = 0.f, a02 = 0.f;
        float a10 = 0.f, a11 = 0.f, a12 = 0.f;
        const float* hep = s_he + f;
        #pragma unroll 4
        for (int j = 0; j < 256; j += 2) {
            float he0 = hep[j * HE_STRIDE];
            float he1 = hep[(j + 1) * HE_STRIDE];
            float at0 = s_att[j * 4 + hd];
            float at1 = s_att[(j + 1) * 4 + hd];
            float w0 = he0 * at0, w1 = he1 * at1;
            agg0 += w0; agg1 += w1;
            a00 += w0 * s_unit[j * 4 + 0];       a10 += w1 * s_unit[(j + 1) * 4 + 0];
            a01 += w0 * s_unit[j * 4 + 1];       a11 += w1 * s_unit[(j + 1) * 4 + 1];
            a02 += w0 * s_unit[j * 4 + 2];       a12 += w1 * s_unit[(j + 1) * 4 + 2];
        }
        s_agg[t] = agg0 + agg1;
        const float invn = 1.0f / 256.0f;
        float c0 = (a00 + a10) * invn, c1 = (a01 + a11) * invn, c2 = (a02 + a12) * invn;
        s_cn[t] = c0 * c0 + c1 * c1 + c2 * c2;
        float vm = vmix_w[t];
        float4 dv = make_float4(vm * c0, vm * c1, vm * c2, 0.0f);
        dv = blockRed4(dv, s_red, false);
        if (t == 0) { s_misc[8] = dv.x; s_misc[9] = dv.y; s_misc[10] = dv.z; }
    }
    __syncthreads();

    // ---- post MLP layer 1: 256-k dot parallelized over all 256 threads ----
    {
        const int q = t >> 6, oo = t & 63;
        float p0 = 0.f, p1 = 0.f;
        const int k0 = q * 64;
        #pragma unroll 8
        for (int k = k0; k < k0 + 64; k += 2) {
            p0 += s_cn[k]     * post_w1[k * 64 + oo];
            p1 += s_cn[k + 1] * post_w1[(k + 1) * 64 + oo];
        }
        s_part[t] = p0 + p1;
    }
    __syncthreads();
    if (t < 64) {
        float acc = post_b1[t] + (s_part[t] + s_part[64 + t]) + (s_part[128 + t] + s_part[192 + t]);
        s_h1[t] = siluf(acc);
    }
    __syncthreads();
    if (t < 64) {
        float acc0 = post_b2[t], acc1 = 0.f;
        #pragma unroll
        for (int k = 0; k < 64; k += 2) {
            acc0 += s_h1[k]     * post_w2[k * 64 + t];
            acc1 += s_h1[k + 1] * post_w2[(k + 1) * 64 + t];
        }
        s_hc[t] = siluf(acc0 + acc1);
    }
    __syncthreads();

    // ---- node MLP layer 1: agg segment parallelized over 256 threads ----
    {
        const int q = t >> 6, oo = t & 63;
        float p0 = 0.f, p1 = 0.f;
        const int k0 = q * 64;
        #pragma unroll 8
        for (int k = k0; k < k0 + 64; k += 2) {
            p0 += s_agg[k]     * node_w1[(64 + k) * 64 + oo];
            p1 += s_agg[k + 1] * node_w1[(64 + k + 1) * 64 + oo];
        }
        s_part[t] = p0 + p1;
    }
    __syncthreads();
    if (t < 64) {
        float acc0 = node_b1[t], acc1 = 0.f;
        #pragma unroll
        for (int k = 0; k < 64; k += 2) {
            acc0 += s_hi[k]     * node_w1[k * 64 + t];
            acc1 += s_hi[k + 1] * node_w1[(k + 1) * 64 + t];
        }
        #pragma unroll
        for (int k = 0; k < 64; k += 2) {
            acc0 += s_hc[k]     * node_w1[(320 + k) * 64 + t];
            acc1 += s_hc[k + 1] * node_w1[(320 + k + 1) * 64 + t];
        }
        float acc = acc0 + acc1 + (s_part[t] + s_part[64 + t]) + (s_part[128 + t] + s_part[192 + t]);
        s_h1[t] = siluf(acc);
    }
    __syncthreads();
    if (t < 64) {
        float acc0 = node_b2[t], acc1 = 0.f;
        #pragma unroll
        for (int k = 0; k < 64; k += 2) {
            acc0 += s_h1[k]     * node_w2[k * 64 + t];
            acc1 += s_h1[k + 1] * node_w2[(k + 1) * 64 + t];
        }
        float hn = s_hi[t] + siluf(acc0 + acc1);
        s_hn[t] = hn;
        out[row_i * 64 + t] = hn;
    }
    __syncthreads();

    // ---- velocity / coordinate update ----
    if (t < 64) {
        float acc0 = vel_b1[t], acc1 = 0.f;
        #pragma unroll
        for (int k = 0; k < 64; k += 2) {
            acc0 += s_hn[k]     * vel_w1[k * 64 + t];
            acc1 += s_hn[k + 1] * vel_w1[(k + 1) * 64 + t];
        }
        float hv = siluf(acc0 + acc1) * vel_w2[t];
        #pragma unroll
        for (int off = 16; off; off >>= 1) hv += __shfl_xor_sync(0xffffffffu, hv, off);
        if ((t & 31) == 0) s_misc[12 + (t >> 5)] = hv;
    }
    __syncthreads();
    if (t < 3) {
        float vs = s_misc[12] + s_misc[13];
        float vnew = s_misc[8 + t] + vs * v[row_i * 3 + t];
        float xnew = x[row_i * 3 + t] + vnew;
        out[Bsz * Nsz * Fsz + row_i * 3 + t] = xnew;
        out[Bsz * Nsz * Fsz + Bsz * Nsz * 3 + row_i * 3 + t] = vnew;
    }
}

// ---------------------------------------------------------------------------
extern "C" void kernel_launch(void* const* d_in, const int* in_sizes, int n_in,
                              void* d_out, int out_size) {
    (void)in_sizes; (void)n_in; (void)out_size;
    const float* h        = (const float*)d_in[0];
    const float* x        = (const float*)d_in[1];
    const float* v        = (const float*)d_in[2];
    const float* edge_w1  = (const float*)d_in[3];
    const float* edge_b1  = (const float*)d_in[4];
    const float* edge_w2  = (const float*)d_in[5];
    const float* edge_b2  = (const float*)d_in[6];
    const float* sem_w    = (const float*)d_in[7];
    const float* sem_b    = (const float*)d_in[8];
    const float* post_w1  = (const float*)d_in[9];
    const float* post_b1  = (const float*)d_in[10];
    const float* post_w2  = (const float*)d_in[11];
    const float* post_b2  = (const float*)d_in[12];
    const float* node_w1  = (const float*)d_in[13];
    const float* node_b1  = (const float*)d_in[14];
    const float* node_w2  = (const float*)d_in[15];
    const float* node_b2  = (const float*)d_in[16];
    const float* vel_w1   = (const float*)d_in[17];
    const float* vel_b1   = (const float*)d_in[18];
    const float* vel_w2   = (const float*)d_in[19];
    const float* vmix_w   = (const float*)d_in[20];
    const float* log_gamma= (const float*)d_in[21];
    float* out = (float*)d_out;

    cudaFuncSetAttribute(sake_main_kernel,
                         cudaFuncAttributeMaxDynamicSharedMemorySize, SMEM_BYTES);

    sake_pre_kernel<<<Bsz * Nsz, 64>>>(h, edge_w1, edge_b1);
    sake_main_kernel<<<Bsz * Nsz, 256, SMEM_BYTES>>>(
        h, x, v, edge_w1, edge_w2, edge_b2, sem_w, sem_b,
        post_w1, post_b1, post_w2, post_b2,
        node_w1, node_b1, node_w2, node_b2,
        vel_w1, vel_b1, vel_w2, vmix_w, log_gamma, out);
}

// round 16
// speedup vs baseline: 1.2223x; 1.0097x over previous
#include <cuda_runtime.h>
#include <math.h>

#define Bsz    2
#define Nsz    256
#define Fsz    64
#define Hsz    64
#define NHEADS 4
#define Csz    256
#define EPSf   1e-5f
#define INFf   1e5f
#define HE_STRIDE 68

__device__ float g_A [Bsz * Nsz * Hsz];
__device__ float g_Bv[Bsz * Nsz * Hsz];

__device__ __forceinline__ float siluf(float xv) {
    return xv / (1.0f + __expf(-xv));
}

// ---------------------------------------------------------------------------
__global__ void sake_pre_kernel(const float* __restrict__ h,
                                const float* __restrict__ edge_w1,
                                const float* __restrict__ edge_b1) {
    int row = blockIdx.x;
    int t = threadIdx.x;
    __shared__ float sh[64];
    sh[t] = h[row * 64 + t];
    __syncthreads();
    float a0 = 0.0f, a1 = 0.0f;
    float b0 = edge_b1[t], b1 = 0.0f;
    #pragma unroll
    for (int k = 0; k < 64; k += 2) {
        float h0 = sh[k], h1 = sh[k + 1];
        a0 += h0 * edge_w1[k * 64 + t];
        a1 += h1 * edge_w1[(k + 1) * 64 + t];
        b0 += h0 * edge_w1[(64 + k) * 64 + t];
        b1 += h1 * edge_w1[(64 + k + 1) * 64 + t];
    }
    g_A [row * 64 + t] = a0 + a1;
    g_Bv[row * 64 + t] = b0 + b1;
}

// ---------------------------------------------------------------------------
__device__ __forceinline__ float4 warpRed4(float4 v, bool is_max) {
    #pragma unroll
    for (int off = 16; off; off >>= 1) {
        float ax = __shfl_xor_sync(0xffffffffu, v.x, off);
        float ay = __shfl_xor_sync(0xffffffffu, v.y, off);
        float az = __shfl_xor_sync(0xffffffffu, v.z, off);
        float aw = __shfl_xor_sync(0xffffffffu, v.w, off);
        if (is_max) { v.x = fmaxf(v.x, ax); v.y = fmaxf(v.y, ay); v.z = fmaxf(v.z, az); v.w = fmaxf(v.w, aw); }
        else        { v.x += ax;            v.y += ay;            v.z += az;            v.w += aw; }
    }
    return v;
}

// scratch: 80 floats (16 float4 stage + 2 float4 results)
__device__ __forceinline__ float4 blockRed4(float4 v, float* scratch, bool is_max) {
    int t = threadIdx.x, lane = t & 31, wid = t >> 5;
    v = warpRed4(v, is_max);
    __syncthreads();
    if (lane == 0) ((float4*)scratch)[wid] = v;
    __syncthreads();
    if (t < 8) {
        float4 w = ((float4*)scratch)[t];
        #pragma unroll
        for (int off = 4; off; off >>= 1) {
            float ax = __shfl_xor_sync(0x000000ffu, w.x, off, 8);
            float ay = __shfl_xor_sync(0x000000ffu, w.y, off, 8);
            float az = __shfl_xor_sync(0x000000ffu, w.z, off, 8);
            float aw = __shfl_xor_sync(0x000000ffu, w.w, off, 8);
            if (is_max) { w.x = fmaxf(w.x, ax); w.y = fmaxf(w.y, ay); w.z = fmaxf(w.z, az); w.w = fmaxf(w.w, aw); }
            else        { w.x += ax;            w.y += ay;            w.z += az;            w.w += aw; }
        }
        if (t == 0) ((float4*)scratch)[16] = w;
    }
    __syncthreads();
    return ((float4*)scratch)[16];
}

// fused reduction of two float4 values (same op), same barrier count as one
__device__ __forceinline__ void blockRed4x2(float4& u, float4& w, float* scratch, bool is_max) {
    int t = threadIdx.x, lane = t & 31, wid = t >> 5;
    u = warpRed4(u, is_max);
    w = warpRed4(w, is_max);
    __syncthreads();
    if (lane == 0) {
        ((float4*)scratch)[wid * 2 + 0] = u;
        ((float4*)scratch)[wid * 2 + 1] = w;
    }
    __syncthreads();
    if (t < 8) {
        float4 a = ((float4*)scratch)[t * 2 + 0];
        float4 b = ((float4*)scratch)[t * 2 + 1];
        #pragma unroll
        for (int off = 4; off; off >>= 1) {
            float x0 = __shfl_xor_sync(0xffu, a.x, off, 8);
            float x1 = __shfl_xor_sync(0xffu, a.y, off, 8);
            float x2 = __shfl_xor_sync(0xffu, a.z, off, 8);
            float x3 = __shfl_xor_sync(0xffu, a.w, off, 8);
            float y0 = __shfl_xor_sync(0xffu, b.x, off, 8);
            float y1 = __shfl_xor_sync(0xffu, b.y, off, 8);
            float y2 = __shfl_xor_sync(0xffu, b.z, off, 8);
            float y3 = __shfl_xor_sync(0xffu, b.w, off, 8);
            if (is_max) {
                a.x = fmaxf(a.x, x0); a.y = fmaxf(a.y, x1); a.z = fmaxf(a.z, x2); a.w = fmaxf(a.w, x3);
                b.x = fmaxf(b.x, y0); b.y = fmaxf(b.y, y1); b.z = fmaxf(b.z, y2); b.w = fmaxf(b.w, y3);
            } else {
                a.x += x0; a.y += x1; a.z += x2; a.w += x3;
                b.x += y0; b.y += y1; b.z += y2; b.w += y3;
            }
        }
        if (t == 0) { ((float4*)scratch)[16] = a; ((float4*)scratch)[17] = b; }
    }
    __syncthreads();
    u = ((float4*)scratch)[16];
    w = ((float4*)scratch)[17];
}

// ---------------------------------------------------------------------------
#define SM_HE    0
#define SM_ACT   (SM_HE   + 256*HE_STRIDE)   // 2 halves x 2 parity x 4 slots x 64 = 1024
#define SM_DIST  (SM_ACT  + 1024)
#define SM_UNIT  (SM_DIST + 256)
#define SM_ATT   (SM_UNIT + 1024)            // reused as s_part in tail
#define SM_BVI   (SM_ATT  + 1024)
#define SM_W1L   (SM_BVI  + 64)
#define SM_B2    (SM_W1L  + 64)
#define SM_SEMW  (SM_B2   + 64)
#define SM_HI    (SM_SEMW + 256)
#define SM_AGG   (SM_HI   + 64)
#define SM_CN    (SM_AGG  + 256)
#define SM_H1    (SM_CN   + 256)
#define SM_HC    (SM_H1   + 64)
#define SM_HN    (SM_HC   + 64)
#define SM_RED   (SM_HN   + 64)              // 80 floats
#define SM_MISC  (SM_RED  + 80)
#define SM_TOTAL (SM_MISC + 16)
#define SMEM_BYTES (SM_TOTAL * 4)

extern __shared__ float smem[];

__global__ __launch_bounds__(256, 2)
void sake_main_kernel(const float* __restrict__ h,
                      const float* __restrict__ x,
                      const float* __restrict__ v,
                      const float* __restrict__ edge_w1,
                      const float* __restrict__ edge_w2,
                      const float* __restrict__ edge_b2,
                      const float* __restrict__ sem_w,
                      const float* __restrict__ sem_b,
                      const float* __restrict__ post_w1,
                      const float* __restrict__ post_b1,
                      const float* __restrict__ post_w2,
                      const float* __restrict__ post_b2,
                      const float* __restrict__ node_w1,
                      const float* __restrict__ node_b1,
                      const float* __restrict__ node_w2,
                      const float* __restrict__ node_b2,
                      const float* __restrict__ vel_w1,
                      const float* __restrict__ vel_b1,
                      const float* __restrict__ vel_w2,
                      const float* __restrict__ vmix_w,
                      const float* __restrict__ log_gamma,
                      float* __restrict__ out) {
    const int blk = blockIdx.x;
    const int b = blk >> 8;
    const int i = blk & 255;
    const int t = threadIdx.x;
    const int row_i = b * Nsz + i;

    float* s_he   = smem + SM_HE;
    float* s_act  = smem + SM_ACT;
    float* s_dist = smem + SM_DIST;
    float* s_unit = smem + SM_UNIT;
    float* s_att  = smem + SM_ATT;
    float* s_part = smem + SM_ATT;       // alias: s_att is dead when s_part is used
    float* s_Bvi  = smem + SM_BVI;
    float* s_w1l  = smem + SM_W1L;
    float* s_b2   = smem + SM_B2;
    float* s_semw = smem + SM_SEMW;
    float* s_hi   = smem + SM_HI;
    float* s_agg  = smem + SM_AGG;
    float* s_cn   = smem + SM_CN;
    float* s_h1   = smem + SM_H1;
    float* s_hc   = smem + SM_HC;
    float* s_hn   = smem + SM_HN;
    float* s_red  = smem + SM_RED;
    float* s_misc = smem + SM_MISC;

    // ---- init ----
    if (t < 64) {
        s_Bvi[t] = g_Bv[row_i * 64 + t];
        s_w1l[t] = edge_w1[128 * 64 + t];
        s_b2 [t] = edge_b2[t];
        s_hi [t] = h[row_i * 64 + t];
    }
    s_semw[t] = sem_w[t];
    if (t < 4) {
        s_misc[t]     = __expf(log_gamma[t]);
        s_misc[4 + t] = sem_b[t];
    }

    {
        const float xi0 = x[row_i * 3 + 0];
        const float xi1 = x[row_i * 3 + 1];
        const float xi2 = x[row_i * 3 + 2];
        const int j = t;
        const int row_j = b * Nsz + j;
        float dx = x[row_j * 3 + 0] - xi0;
        float dy = x[row_j * 3 + 1] - xi1;
        float dz = x[row_j * 3 + 2] - xi2;
        float xn = sqrtf(dx * dx + dy * dy + dz * dz + EPSf);
        s_dist[j] = xn;
        float inv = 1.0f / (xn + EPSf);
        s_unit[j * 4 + 0] = dx * inv;
        s_unit[j * 4 + 1] = dy * inv;
        s_unit[j * 4 + 2] = dz * inv;
        s_unit[j * 4 + 3] = 0.0f;
    }

    for (int idx = t; idx < 256 * 64; idx += 256) {
        int j = idx >> 6, o = idx & 63;
        s_he[j * HE_STRIDE + o] = g_A[b * Nsz * 64 + idx];
    }

    const int o    = t & 63;
    const int jl   = (t >> 6) & 1;
    const int half = t >> 7;
    float w2[64];
    #pragma unroll
    for (int k = 0; k < 64; k++) w2[k] = edge_w2[k * 64 + o];
    __syncthreads();

    // hoisted invariants (after barrier so producers are done)
    const float rBvi = s_Bvi[o];
    const float rw1l = s_w1l[o];
    const float rb2  = s_b2[o];

    // ---- edge MLP: two independent 128-thread halves, 4 j per half per iter,
    //      2 j per thread, named barriers, double-buffered act.
    //      Inner unroll limited to 2 float4-pairs to keep regs < 128 (no spill).
    {
        const int jbase = half * 128;
        const int barid = 1 + half;
        for (int it = 0; it < 32; it++) {
            const int jA = jbase + it * 4 + jl;
            const int jB = jA + 2;
            float* actb = s_act + half * 512 + (it & 1) * 256;
            float preA = s_he[jA * HE_STRIDE + o] + rBvi + s_dist[jA] * rw1l;
            float preB = s_he[jB * HE_STRIDE + o] + rBvi + s_dist[jB] * rw1l;
            actb[jl * 64 + o]       = siluf(preA);
            actb[(2 + jl) * 64 + o] = siluf(preB);
            asm volatile("bar.sync %0, %1;" :: "r"(barid), "r"(128) : "memory");
            float a0 = 0.f, a1 = 0.f;
            float b0 = 0.f, b1 = 0.f;
            const float4* aA = (const float4*)(actb + jl * 64);
            const float4* aB = (const float4*)(actb + (2 + jl) * 64);
            #pragma unroll
            for (int k4 = 0; k4 < 16; k4 += 2) {
                float4 vA0 = aA[k4],     vB0 = aB[k4];
                float4 vA1 = aA[k4 + 1], vB1 = aB[k4 + 1];
                const float* wp = w2 + 4 * k4;
                a0 += vA0.x * wp[0] + vA0.y * wp[1] + vA0.z * wp[2] + vA0.w * wp[3];
                b0 += vB0.x * wp[0] + vB0.y * wp[1] + vB0.z * wp[2] + vB0.w * wp[3];
                a1 += vA1.x * wp[4] + vA1.y * wp[5] + vA1.z * wp[6] + vA1.w * wp[7];
                b1 += vB1.x * wp[4] + vB1.y * wp[5] + vB1.z * wp[6] + vB1.w * wp[7];
            }
            s_he[jA * HE_STRIDE + o] = siluf(rb2 + a0 + a1);
            s_he[jB * HE_STRIDE + o] = siluf(rb2 + b0 + b1);
        }
    }
    __syncthreads();

    // ---- semantic logits + three chained softmaxes (thread j = t) ----
    {
        const int j = t;
        const float4* her = (const float4*)(s_he + j * HE_STRIDE);
        const float4* sw  = (const float4*)s_semw;
        float4 sl = make_float4(s_misc[4], s_misc[5], s_misc[6], s_misc[7]);
        #pragma unroll
        for (int k4 = 0; k4 < 16; k4++) {
            float4 hv = her[k4];
            float4 wa = sw[4 * k4 + 0];
            float4 wb = sw[4 * k4 + 1];
            float4 wc = sw[4 * k4 + 2];
            float4 wd = sw[4 * k4 + 3];
            sl.x += hv.x * wa.x + hv.y * wb.x + hv.z * wc.x + hv.w * wd.x;
            sl.y += hv.x * wa.y + hv.y * wb.y + hv.z * wc.y + hv.w * wd.y;
            sl.z += hv.x * wa.z + hv.y * wb.z + hv.z * wc.z + hv.w * wd.z;
            sl.w += hv.x * wa.w + hv.y * wb.w + hv.z * wc.w + hv.w * wd.w;
        }
        sl.x = (sl.x > 0.0f ? sl.x : 0.2f * sl.x);
        sl.y = (sl.y > 0.0f ? sl.y : 0.2f * sl.y);
        sl.z = (sl.z > 0.0f ? sl.z : 0.2f * sl.z);
        sl.w = (sl.w > 0.0f ? sl.w : 0.2f * sl.w);
        const float diag = (j == i) ? INFf : 0.0f;
        sl.x -= diag; sl.y -= diag; sl.z -= diag; sl.w -= diag;

        const float dmask = s_dist[j] + diag;
        float4 dl = make_float4(-dmask * s_misc[0], -dmask * s_misc[1],
                                -dmask * s_misc[2], -dmask * s_misc[3]);

        // fused max(dl), max(sl)
        float4 mdl = dl, msl = sl;
        blockRed4x2(mdl, msl, s_red, true);
        float4 eu = make_float4(__expf(dl.x - mdl.x), __expf(dl.y - mdl.y),
                                __expf(dl.z - mdl.z), __expf(dl.w - mdl.w));
        float4 se = make_float4(__expf(sl.x - msl.x), __expf(sl.y - msl.y),
                                __expf(sl.z - msl.z), __expf(sl.w - msl.w));
        // fused sum(eu), sum(se)
        float4 seu = eu, sse = se;
        blockRed4x2(seu, sse, s_red, false);
        eu.x /= seu.x; eu.y /= seu.y; eu.z /= seu.z; eu.w /= seu.w;
        se.x /= sse.x; se.y /= sse.y; se.z /= sse.z; se.w /= sse.w;

        float4 cl = make_float4(eu.x * se.x, eu.y * se.y, eu.z * se.z, eu.w * se.w);
        float4 m = blockRed4(cl, s_red, true);
        float4 ce = make_float4(__expf(cl.x - m.x), __expf(cl.y - m.y),
                                __expf(cl.z - m.z), __expf(cl.w - m.w));
        float4 sm = blockRed4(ce, s_red, false);
        s_att[j * 4 + 0] = ce.x / sm.x;
        s_att[j * 4 + 1] = ce.y / sm.y;
        s_att[j * 4 + 2] = ce.z / sm.z;
        s_att[j * 4 + 3] = ce.w / sm.w;
    }
    __syncthreads();

    // ---- weighted aggregations (thread c = t) ----
    {
        const int f  = t >> 2;
        const int hd = t & 3;
        float agg0 = 0.f, agg1 = 0.f;
        float a00 = 0.f, a01 = 0.f, a02 = 0.f;
        float a10 = 0.f, a11 = 0.f, a12 = 0.f;
        const float* hep = s_he + f;
        #pragma unroll 4
        for (int j = 0; j < 256; j += 2) {
            float he0 = hep[j * HE_STRIDE];
            float he1 = hep[(j + 1) * HE_STRIDE];
            float at0 = s_att[j * 4 + hd];
            float at1 = s_att[(j + 1) * 4 + hd];
            float w0 = he0 * at0, w1 = he1 * at1;
            agg0 += w0; agg1 += w1;
            a00 += w0 * s_unit[j * 4 + 0];       a10 += w1 * s_unit[(j + 1) * 4 + 0];
            a01 += w0 * s_unit[j * 4 + 1];       a11 += w1 * s_unit[(j + 1) * 4 + 1];
            a02 += w0 * s_unit[j * 4 + 2];       a12 += w1 * s_unit[(j + 1) * 4 + 2];
        }
        s_agg[t] = agg0 + agg1;
        const float invn = 1.0f / 256.0f;
        float c0 = (a00 + a10) * invn, c1 = (a01 + a11) * invn, c2 = (a02 + a12) * invn;
        s_cn[t] = c0 * c0 + c1 * c1 + c2 * c2;
        float vm = vmix_w[t];
        float4 dv = make_float4(vm * c0, vm * c1, vm * c2, 0.0f);
        dv = blockRed4(dv, s_red, false);
        if (t == 0) { s_misc[8] = dv.x; s_misc[9] = dv.y; s_misc[10] = dv.z; }
    }
    __syncthreads();

    // ---- post MLP layer 1: 256-k dot parallelized over all 256 threads ----
    {
        const int q = t >> 6, oo = t & 63;
        float p0 = 0.f, p1 = 0.f;
        const int k0 = q * 64;
        #pragma unroll 8
        for (int k = k0; k < k0 + 64; k += 2) {
            p0 += s_cn[k]     * post_w1[k * 64 + oo];
            p1 += s_cn[k + 1] * post_w1[(k + 1) * 64 + oo];
        }
        s_part[t] = p0 + p1;
    }
    __syncthreads();
    if (t < 64) {
        float acc = post_b1[t] + (s_part[t] + s_part[64 + t]) + (s_part[128 + t] + s_part[192 + t]);
        s_h1[t] = siluf(acc);
    }
    __syncthreads();
    if (t < 64) {
        float acc0 = post_b2[t], acc1 = 0.f;
        #pragma unroll
        for (int k = 0; k < 64; k += 2) {
            acc0 += s_h1[k]     * post_w2[k * 64 + t];
            acc1 += s_h1[k + 1] * post_w2[(k + 1) * 64 + t];
        }
        s_hc[t] = siluf(acc0 + acc1);
    }
    __syncthreads();

    // ---- node MLP layer 1: agg segment parallelized over 256 threads ----
    {
        const int q = t >> 6, oo = t & 63;
        float p0 = 0.f, p1 = 0.f;
        const int k0 = q * 64;
        #pragma unroll 8
        for (int k = k0; k < k0 + 64; k += 2) {
            p0 += s_agg[k]     * node_w1[(64 + k) * 64 + oo];
            p1 += s_agg[k + 1] * node_w1[(64 + k + 1) * 64 + oo];
        }
        s_part[t] = p0 + p1;
    }
    __syncthreads();
    if (t < 64) {
        float acc0 = node_b1[t], acc1 = 0.f;
        #pragma unroll
        for (int k = 0; k < 64; k += 2) {
            acc0 += s_hi[k]     * node_w1[k * 64 + t];
            acc1 += s_hi[k + 1] * node_w1[(k + 1) * 64 + t];
        }
        #pragma unroll
        for (int k = 0; k < 64; k += 2) {
            acc0 += s_hc[k]     * node_w1[(320 + k) * 64 + t];
            acc1 += s_hc[k + 1] * node_w1[(320 + k + 1) * 64 + t];
        }
        float acc = acc0 + acc1 + (s_part[t] + s_part[64 + t]) + (s_part[128 + t] + s_part[192 + t]);
        s_h1[t] = siluf(acc);
    }
    __syncthreads();
    if (t < 64) {
        float acc0 = node_b2[t], acc1 = 0.f;
        #pragma unroll
        for (int k = 0; k < 64; k += 2) {
            acc0 += s_h1[k]     * node_w2[k * 64 + t];
            acc1 += s_h1[k + 1] * node_w2[(k + 1) * 64 + t];
        }
        float hn = s_hi[t] + siluf(acc0 + acc1);
        s_hn[t] = hn;
        out[row_i * 64 + t] = hn;
    }
    __syncthreads();

    // ---- velocity / coordinate update ----
    if (t < 64) {
        float acc0 = vel_b1[t], acc1 = 0.f;
        #pragma unroll
        for (int k = 0; k < 64; k += 2) {
            acc0 += s_hn[k]     * vel_w1[k * 64 + t];
            acc1 += s_hn[k + 1] * vel_w1[(k + 1) * 64 + t];
        }
        float hv = siluf(acc0 + acc1) * vel_w2[t];
        #pragma unroll
        for (int off = 16; off; off >>= 1) hv += __shfl_xor_sync(0xffffffffu, hv, off);
        if ((t & 31) == 0) s_misc[12 + (t >> 5)] = hv;
    }
    __syncthreads();
    if (t < 3) {
        float vs = s_misc[12] + s_misc[13];
        float vnew = s_misc[8 + t] + vs * v[row_i * 3 + t];
        float xnew = x[row_i * 3 + t] + vnew;
        out[Bsz * Nsz * Fsz + row_i * 3 + t] = xnew;
        out[Bsz * Nsz * Fsz + Bsz * Nsz * 3 + row_i * 3 + t] = vnew;
    }
}

// ---------------------------------------------------------------------------
extern "C" void kernel_launch(void* const* d_in, const int* in_sizes, int n_in,
                              void* d_out, int out_size) {
    (void)in_sizes; (void)n_in; (void)out_size;
    const float* h        = (const float*)d_in[0];
    const float* x        = (const float*)d_in[1];
    const float* v        = (const float*)d_in[2];
    const float* edge_w1  = (const float*)d_in[3];
    const float* edge_b1  = (const float*)d_in[4];
    const float* edge_w2  = (const float*)d_in[5];
    const float* edge_b2  = (const float*)d_in[6];
    const float* sem_w    = (const float*)d_in[7];
    const float* sem_b    = (const float*)d_in[8];
    const float* post_w1  = (const float*)d_in[9];
    const float* post_b1  = (const float*)d_in[10];
    const float* post_w2  = (const float*)d_in[11];
    const float* post_b2  = (const float*)d_in[12];
    const float* node_w1  = (const float*)d_in[13];
    const float* node_b1  = (const float*)d_in[14];
    const float* node_w2  = (const float*)d_in[15];
    const float* node_b2  = (const float*)d_in[16];
    const float* vel_w1   = (const float*)d_in[17];
    const float* vel_b1   = (const float*)d_in[18];
    const float* vel_w2   = (const float*)d_in[19];
    const float* vmix_w   = (const float*)d_in[20];
    const float* log_gamma= (const float*)d_in[21];
    float* out = (float*)d_out;

    cudaFuncSetAttribute(sake_main_kernel,
                         cudaFuncAttributeMaxDynamicSharedMemorySize, SMEM_BYTES);

    sake_pre_kernel<<<Bsz * Nsz, 64>>>(h, edge_w1, edge_b1);
    sake_main_kernel<<<Bsz * Nsz, 256, SMEM_BYTES>>>(
        h, x, v, edge_w1, edge_w2, edge_b2, sem_w, sem_b,
        post_w1, post_b1, post_w2, post_b2,
        node_w1, node_b1, node_w2, node_b2,
        vel_w1, vel_b1, vel_w2, vmix_w, log_gamma, out);
}